// round 2
// baseline (speedup 1.0000x reference)
#include <cuda_runtime.h>
#include <math.h>

// B=8, N=128, D=256
#define NB 8
#define NN 128
#define ND 256
#define BN2 1024           // B*N
#define ROWS_E 131072      // B*N*N

// ---------------- scratch (device globals; no allocation allowed) -------------
__device__ float g_pre1[67108864];   // [B*N*N, 512]: cols 0..255 = e1_fuse, 256..511 = e1_fc
__device__ float g_pre2[67108864];   // same for edge2
__device__ float g_W1cat[256 * 512];
__device__ float g_W2cat[256 * 512];
__device__ float g_Wproj[256 * 1536];
__device__ float g_P[1024 * 1536];   // projections of `out`: [A1|B1|A2|B2|U1|U2]
__device__ float g_out[1024 * 256];
__device__ float g_OC[1024 * 512];   // [out1 | out2]
__device__ float g_H[1024 * 256];
__device__ float g_AS1[131072];      // adj1 * sigmoid(s1)
__device__ float g_AS2[131072];

// ---------------- helpers ----------------------------------------------------
__device__ __forceinline__ float blockSum256(float v) {
    __shared__ float red[8];
    #pragma unroll
    for (int o = 16; o; o >>= 1) v += __shfl_xor_sync(0xffffffffu, v, o);
    if ((threadIdx.x & 31) == 0) red[threadIdx.x >> 5] = v;
    __syncthreads();
    float s = red[0];
    #pragma unroll
    for (int k = 1; k < 8; k++) s += red[k];
    __syncthreads();
    return s;
}

// ---------------- weight repack ----------------------------------------------
__global__ void repack_edge_w(const float* __restrict__ fuse_w,
                              const float* __restrict__ fc_w0,
                              float* __restrict__ Wcat) {
    int k = blockIdx.x;    // 0..255
    int n = threadIdx.x;   // 0..511
    float v = (n < 256) ? fuse_w[(256 + k) * 256 + n]
                        : fc_w0[(512 + k) * 256 + (n - 256)];
    Wcat[k * 512 + n] = v;
}

__global__ void repack_proj_w(const float* __restrict__ fc1_w0,
                              const float* __restrict__ fc2_w0,
                              const float* __restrict__ fuse1_w,
                              const float* __restrict__ fuse2_w,
                              float* __restrict__ W) {
    int k = blockIdx.x;    // 0..255
    int c = threadIdx.x;   // 0..255
    W[k * 1536 + 0    + c] = fc1_w0[k * 256 + c];
    W[k * 1536 + 256  + c] = fc1_w0[(256 + k) * 256 + c];
    W[k * 1536 + 512  + c] = fc2_w0[k * 256 + c];
    W[k * 1536 + 768  + c] = fc2_w0[(256 + k) * 256 + c];
    W[k * 1536 + 1024 + c] = fuse1_w[k * 256 + c];
    W[k * 1536 + 1280 + c] = fuse2_w[k * 256 + c];
}

// ---------------- generic fp32 SGEMM: C[M,N] = A[M,K] @ W[K,N] ----------------
// 128x128 tile, BK=8, 256 threads, 8x8 per thread. M,N % 128 == 0, K % 8 == 0.
__global__ __launch_bounds__(256) void sgemm128(
    const float* __restrict__ A, const float* __restrict__ Bm,
    float* __restrict__ C, int M, int N, int K, int doRelu) {
    __shared__ float As[8][132];
    __shared__ float Bs[8][128];
    const int tid = threadIdx.x;
    const int bx = blockIdx.x, by = blockIdx.y;
    const int tx = tid & 15, ty = tid >> 4;
    const int a_row = tid >> 1;
    const int a_col = (tid & 1) * 4;
    const int b_row = tid >> 5;
    const int b_col = (tid & 31) * 4;
    const float* Ab = A + (size_t)by * 128 * K;
    const float* Bb = Bm + (size_t)bx * 128;

    float acc[8][8];
    #pragma unroll
    for (int i = 0; i < 8; i++)
        #pragma unroll
        for (int j = 0; j < 8; j++) acc[i][j] = 0.f;

    for (int kk = 0; kk < K; kk += 8) {
        float4 av = *(const float4*)(Ab + (size_t)a_row * K + kk + a_col);
        float4 bv = *(const float4*)(Bb + (size_t)(kk + b_row) * N + b_col);
        As[a_col + 0][a_row] = av.x;
        As[a_col + 1][a_row] = av.y;
        As[a_col + 2][a_row] = av.z;
        As[a_col + 3][a_row] = av.w;
        *(float4*)&Bs[b_row][b_col] = bv;
        __syncthreads();
        #pragma unroll
        for (int k = 0; k < 8; k++) {
            float ar[8], br[8];
            #pragma unroll
            for (int i = 0; i < 8; i++) ar[i] = As[k][ty * 8 + i];
            #pragma unroll
            for (int j = 0; j < 8; j++) br[j] = Bs[k][tx * 8 + j];
            #pragma unroll
            for (int i = 0; i < 8; i++)
                #pragma unroll
                for (int j = 0; j < 8; j++)
                    acc[i][j] = fmaf(ar[i], br[j], acc[i][j]);
        }
        __syncthreads();
    }
    #pragma unroll
    for (int i = 0; i < 8; i++) {
        size_t coff = (size_t)(by * 128 + ty * 8 + i) * N + bx * 128 + tx * 8;
        #pragma unroll
        for (int j0 = 0; j0 < 8; j0 += 4) {
            float4 v;
            v.x = acc[i][j0 + 0]; v.y = acc[i][j0 + 1];
            v.z = acc[i][j0 + 2]; v.w = acc[i][j0 + 3];
            if (doRelu) {
                v.x = fmaxf(v.x, 0.f); v.y = fmaxf(v.y, 0.f);
                v.z = fmaxf(v.z, 0.f); v.w = fmaxf(v.w, 0.f);
            }
            *(float4*)(C + coff + j0) = v;
        }
    }
}

// ---------------- score: AS = adj * sigmoid(relu(ti+tj+e_fc)@w1 + b1) ---------
// one warp per (b,i,j)
__global__ __launch_bounds__(256) void score_kernel(
    const float* __restrict__ P,
    const float* __restrict__ adj1, const float* __restrict__ adj2,
    const float* __restrict__ fc1_w1, const float* __restrict__ fc2_w1,
    const float* __restrict__ fc1_b1, const float* __restrict__ fc2_b1,
    float* __restrict__ AS1, float* __restrict__ AS2) {
    int gw = blockIdx.x * 8 + (threadIdx.x >> 5);   // (b*N + i)*N + j
    int lane = threadIdx.x & 31;
    int j = gw & 127;
    int bi = gw >> 7;            // b*N + i
    int b = gw >> 14;
    const float* Pi = P + (size_t)bi * 1536;
    const float* Pj = P + (size_t)(b * 128 + j) * 1536;
    const float* e1 = g_pre1 + (size_t)gw * 512 + 256;
    const float* e2 = g_pre2 + (size_t)gw * 512 + 256;
    float s1 = 0.f, s2 = 0.f;
    #pragma unroll
    for (int t = 0; t < 8; t++) {
        int d = lane + 32 * t;
        float r1 = Pi[d]       + Pj[256 + d] + e1[d];
        float r2 = Pi[512 + d] + Pj[768 + d] + e2[d];
        s1 = fmaf(fmaxf(r1, 0.f), fc1_w1[d], s1);
        s2 = fmaf(fmaxf(r2, 0.f), fc2_w1[d], s2);
    }
    #pragma unroll
    for (int o = 16; o; o >>= 1) {
        s1 += __shfl_xor_sync(0xffffffffu, s1, o);
        s2 += __shfl_xor_sync(0xffffffffu, s2, o);
    }
    if (lane == 0) {
        float v1 = 1.f / (1.f + __expf(-(s1 + fc1_b1[0])));
        float v2 = 1.f / (1.f + __expf(-(s2 + fc2_b1[0])));
        AS1[gw] = adj1[gw] * v1;
        AS2[gw] = adj2[gw] * v2;
    }
}

// ---------------- aggregate: out1/out2 per (b,i) ------------------------------
__global__ __launch_bounds__(256) void aggregate_kernel(
    const float* __restrict__ P,
    const float* __restrict__ AS1, const float* __restrict__ AS2,
    const float* __restrict__ adj1, const float* __restrict__ adj2,
    float* __restrict__ OC) {
    int bid = blockIdx.x;            // b*N + i
    int tid = threadIdx.x;           // d
    int b = bid >> 7;
    __shared__ float w1s[128], w2s[128], sred[8];
    float d1 = 0.f, d2 = 0.f;
    if (tid < 128) {
        w1s[tid] = AS1[bid * 128 + tid];
        w2s[tid] = AS2[bid * 128 + tid];
        d1 = adj1[bid * 128 + tid];
        d2 = adj2[bid * 128 + tid];
    }
    #pragma unroll
    for (int o = 16; o; o >>= 1) {
        d1 += __shfl_xor_sync(0xffffffffu, d1, o);
        d2 += __shfl_xor_sync(0xffffffffu, d2, o);
    }
    if (tid < 128 && (tid & 31) == 0) {
        sred[tid >> 5] = d1;
        sred[4 + (tid >> 5)] = d2;
    }
    __syncthreads();
    float denom1 = sred[0] + sred[1] + sred[2] + sred[3] + 1.0f;
    float denom2 = sred[4] + sred[5] + sred[6] + sred[7] + 1.0f;

    float acc1 = 0.f, acc2 = 0.f;
    const float* Pb = P + (size_t)(b * 128) * 1536;
    const float* e1 = g_pre1 + (size_t)bid * 128 * 512;
    const float* e2 = g_pre2 + (size_t)bid * 128 * 512;
    for (int j = 0; j < 128; j++) {
        float u1 = Pb[j * 1536 + 1024 + tid];
        float u2 = Pb[j * 1536 + 1280 + tid];
        float f1 = e1[j * 512 + tid];
        float f2 = e2[j * 512 + tid];
        acc1 = fmaf(w1s[j], fmaxf(u1 + f1, 0.f), acc1);
        acc2 = fmaf(w2s[j], fmaxf(u2 + f2, 0.f), acc2);
    }
    OC[(size_t)bid * 512 + tid]       = acc1 / denom1;
    OC[(size_t)bid * 512 + 256 + tid] = acc2 / denom2;
}

// ---------------- relu + residual + bias + layernorm --------------------------
__global__ __launch_bounds__(256) void ln_kernel(
    const float* __restrict__ H, const float* __restrict__ prev,
    const float* __restrict__ bias, const float* __restrict__ gamma,
    const float* __restrict__ beta, float* __restrict__ dst) {
    int row = blockIdx.x, tid = threadIdx.x;
    float v = fmaxf(H[(size_t)row * 256 + tid], 0.f)
              + prev[(size_t)row * 256 + tid] + bias[tid];
    float mean = blockSum256(v) * (1.0f / 256.0f);
    float c = v - mean;
    float var = blockSum256(c * c) * (1.0f / 256.0f);
    dst[(size_t)row * 256 + tid] = c * rsqrtf(var + 1e-5f) * gamma[tid] + beta[tid];
}

// ---------------- self-alignment: outss --------------------------------------
__global__ __launch_bounds__(256) void align_kernel(
    const float* __restrict__ text, const float* __restrict__ textmask,
    const float* __restrict__ AL, const float* __restrict__ abias,
    float* __restrict__ outss) {
    int bid = blockIdx.x;    // b*N + i
    int b = bid >> 7;
    int tid = threadIdx.x;
    __shared__ float xi[256], q[256], lg[128], sred[2];
    xi[tid] = text[(size_t)bid * 256 + tid];
    __syncthreads();
    float acc = 0.f;
    #pragma unroll 4
    for (int k = 0; k < 256; k++) acc = fmaf(xi[k], AL[k * 256 + tid], acc);
    q[tid] = acc;
    __syncthreads();

    int w = tid >> 5, lane = tid & 31;
    for (int j = w * 16; j < w * 16 + 16; j++) {
        const float* tj = text + (size_t)(b * 128 + j) * 256;
        float a = 0.f;
        #pragma unroll
        for (int t = 0; t < 8; t++) {
            int d = lane + 32 * t;
            a = fmaf(q[d], tj[d], a);
        }
        #pragma unroll
        for (int o = 16; o; o >>= 1) a += __shfl_xor_sync(0xffffffffu, a, o);
        if (lane == 0)
            lg[j] = a + (1.0f - textmask[b * 128 + j]) * -1e20f;
    }
    __syncthreads();
    if (tid < 32) {
        float m = -3.4e38f;
        for (int k = tid; k < 128; k += 32) m = fmaxf(m, lg[k]);
        #pragma unroll
        for (int o = 16; o; o >>= 1) m = fmaxf(m, __shfl_xor_sync(0xffffffffu, m, o));
        if (tid == 0) sred[0] = m;
    }
    __syncthreads();
    float mx = sred[0];
    if (tid < 128) lg[tid] = __expf(lg[tid] - mx);
    __syncthreads();
    if (tid < 32) {
        float s = 0.f;
        for (int k = tid; k < 128; k += 32) s += lg[k];
        #pragma unroll
        for (int o = 16; o; o >>= 1) s += __shfl_xor_sync(0xffffffffu, s, o);
        if (tid == 0) sred[1] = s;
    }
    __syncthreads();
    float inv = 1.0f / sred[1];
    float a2 = 0.f;
    for (int j = 0; j < 128; j++)
        a2 = fmaf(lg[j], text[(size_t)(b * 128 + j) * 256 + tid], a2);
    outss[(size_t)bid * 256 + tid] = a2 * inv * textmask[bid] + abias[tid];
}

// ---------------- launch ------------------------------------------------------
extern "C" void kernel_launch(void* const* d_in, const int* in_sizes, int n_in,
                              void* d_out, int out_size) {
    const float* text      = (const float*)d_in[0];
    const float* adj1      = (const float*)d_in[1];
    const float* adj2      = (const float*)d_in[2];
    const float* edge1     = (const float*)d_in[3];
    const float* edge2     = (const float*)d_in[4];
    const float* textmask  = (const float*)d_in[5];
    const float* weight    = (const float*)d_in[6];
    const float* bias      = (const float*)d_in[7];
    const float* gamma     = (const float*)d_in[8];
    const float* beta      = (const float*)d_in[9];
    const float* fuse1_w   = (const float*)d_in[10];
    const float* fuse2_w   = (const float*)d_in[11];
    const float* fc3_w     = (const float*)d_in[12];
    const float* fc1_w0    = (const float*)d_in[13];
    const float* fc1_w1    = (const float*)d_in[14];
    const float* fc1_b1    = (const float*)d_in[15];
    const float* fc2_w0    = (const float*)d_in[16];
    const float* fc2_w1    = (const float*)d_in[17];
    const float* fc2_b1    = (const float*)d_in[18];
    const float* align_lin = (const float*)d_in[19];
    const float* align_bias= (const float*)d_in[20];
    float* out = (float*)d_out;

    float *p_pre1, *p_pre2, *p_W1, *p_W2, *p_Wp, *p_P, *p_out, *p_OC, *p_H,
          *p_AS1, *p_AS2;
    cudaGetSymbolAddress((void**)&p_pre1, g_pre1);
    cudaGetSymbolAddress((void**)&p_pre2, g_pre2);
    cudaGetSymbolAddress((void**)&p_W1,   g_W1cat);
    cudaGetSymbolAddress((void**)&p_W2,   g_W2cat);
    cudaGetSymbolAddress((void**)&p_Wp,   g_Wproj);
    cudaGetSymbolAddress((void**)&p_P,    g_P);
    cudaGetSymbolAddress((void**)&p_out,  g_out);
    cudaGetSymbolAddress((void**)&p_OC,   g_OC);
    cudaGetSymbolAddress((void**)&p_H,    g_H);
    cudaGetSymbolAddress((void**)&p_AS1,  g_AS1);
    cudaGetSymbolAddress((void**)&p_AS2,  g_AS2);

    // weight repacks
    repack_edge_w<<<256, 512>>>(fuse1_w, fc1_w0, p_W1);
    repack_edge_w<<<256, 512>>>(fuse2_w, fc2_w0, p_W2);
    repack_proj_w<<<256, 256>>>(fc1_w0, fc2_w0, fuse1_w, fuse2_w, p_Wp);

    // out = relu(text @ weight)
    sgemm128<<<dim3(2, 8), 256>>>(text, weight, p_out, BN2, 256, 256, 1);

    // loop-invariant edge projections (dominant GEMMs)
    sgemm128<<<dim3(4, 1024), 256>>>(edge1, p_W1, p_pre1, ROWS_E, 512, 256, 0);
    sgemm128<<<dim3(4, 1024), 256>>>(edge2, p_W2, p_pre2, ROWS_E, 512, 256, 0);

    // independent self-alignment output
    align_kernel<<<BN2, 256>>>(text, textmask, align_lin, align_bias,
                               out + BN2 * 256);

    for (int it = 0; it < 3; it++) {
        // 6 fused projections of out: P = out @ Wproj
        sgemm128<<<dim3(12, 8), 256>>>(p_out, p_Wp, p_P, BN2, 1536, 256, 0);
        score_kernel<<<ROWS_E / 8, 256>>>(p_P, adj1, adj2, fc1_w1, fc2_w1,
                                          fc1_b1, fc2_b1, p_AS1, p_AS2);
        aggregate_kernel<<<BN2, 256>>>(p_P, p_AS1, p_AS2, adj1, adj2, p_OC);
        // H = [out1|out2] @ fc3_w
        sgemm128<<<dim3(2, 8), 256>>>(p_OC, fc3_w, p_H, BN2, 256, 512, 0);
        float* dst = (it == 2) ? out : p_out;
        ln_kernel<<<BN2, 256>>>(p_H, p_out, bias, gamma, beta, dst);
    }
}

// round 4
// speedup vs baseline: 2.2519x; 2.2519x over previous
#include <cuda_runtime.h>
#include <cuda_bf16.h>
#include <math.h>
#include <stdint.h>

// B=8, N=128, D=256
#define NB 8
#define NN 128
#define ND 256
#define BN2 1024           // B*N
#define ROWS_E 131072      // B*N*N

// ---------------- scratch (device globals; no allocation allowed) -------------
__device__ float g_pre1[67108864];   // [B*N*N, 512] fp32: 0..255 fuse, 256..511 fc
__device__ float g_pre2[67108864];
__device__ float g_Wt1[512 * 256];   // [N][K], tf32-rounded fp32
__device__ float g_Wt2[512 * 256];
__device__ float g_WtP[1536 * 256];
__device__ float g_Wt3[256 * 512];
__device__ float g_Wtw[256 * 256];
__device__ float g_P[1024 * 1536];   // projections of `out`: [A1|B1|A2|B2|U1|U2]
__device__ float g_out[1024 * 256];
__device__ float g_OC[1024 * 512];   // [out1 | out2]
__device__ float g_H[1024 * 256];
__device__ float g_AS1[131072];      // adj1 * sigmoid(s1)
__device__ float g_AS2[131072];

// ---------------- helpers ----------------------------------------------------
__device__ __forceinline__ float blockSum256(float v) {
    __shared__ float red[8];
    #pragma unroll
    for (int o = 16; o; o >>= 1) v += __shfl_xor_sync(0xffffffffu, v, o);
    if ((threadIdx.x & 31) == 0) red[threadIdx.x >> 5] = v;
    __syncthreads();
    float s = red[0];
    #pragma unroll
    for (int k = 1; k < 8; k++) s += red[k];
    __syncthreads();
    return s;
}

__device__ __forceinline__ uint32_t f2tf32(float x) {
    uint32_t r;
    asm("cvt.rna.tf32.f32 %0, %1;" : "=r"(r) : "f"(x));
    return r;
}

__device__ __forceinline__ void mma_tf32(float* d, const uint32_t* a, const uint32_t* b) {
    asm volatile(
        "mma.sync.aligned.m16n8k8.row.col.f32.tf32.tf32.f32 "
        "{%0,%1,%2,%3}, {%4,%5,%6,%7}, {%8,%9}, {%0,%1,%2,%3};\n"
        : "+f"(d[0]), "+f"(d[1]), "+f"(d[2]), "+f"(d[3])
        : "r"(a[0]), "r"(a[1]), "r"(a[2]), "r"(a[3]), "r"(b[0]), "r"(b[1]));
}

// ---------------- weight repack: dst[n][k] = tf32(src[k*256 + n]) -------------
__global__ void repackT(const float* __restrict__ src, float* __restrict__ dst,
                        int K) {
    int n = blockIdx.x;     // 0..255 (segment-local column)
    int k = threadIdx.x;    // 0..K-1
    uint32_t v = f2tf32(src[k * 256 + n]);
    dst[n * K + k] = __uint_as_float(v);
}

// ---------------- tf32 tensor GEMM: C[M,N] = A_f32[M,K] @ Wt[N,K]^T -----------
// 128x128 tile, BK=32, 256 threads (8 warps, 2x4), each warp 64x32 via
// m16n8k8 tf32 mma. A rounded to tf32 on the smem-store path; Wt pre-rounded.
__global__ __launch_bounds__(256, 2) void tgemm(
    const float* __restrict__ A, const float* __restrict__ Wt,
    float* __restrict__ C, int M, int N, int K, int doRelu) {
    __shared__ uint32_t As[128][36];
    __shared__ uint32_t Bs[128][36];
    const int tid = threadIdx.x;
    const int wid = tid >> 5, lane = tid & 31;
    const int g = lane >> 2, qt = lane & 3;
    const int warp_m = wid & 1, warp_n = wid >> 1;
    const int row0 = blockIdx.y * 128;
    const int col0 = blockIdx.x * 128;

    float acc[4][4][4];
    #pragma unroll
    for (int i = 0; i < 4; i++)
        #pragma unroll
        for (int j = 0; j < 4; j++)
            #pragma unroll
            for (int r = 0; r < 4; r++) acc[i][j][r] = 0.f;

    for (int kk = 0; kk < K; kk += 32) {
        // A tile: 128 rows x 32 k, fp32 -> tf32 round on store
        #pragma unroll
        for (int i = 0; i < 4; i++) {
            int idx = tid + 256 * i;
            int r = idx >> 3, c = (idx & 7) * 4;
            float4 v = *(const float4*)(A + (size_t)(row0 + r) * K + kk + c);
            As[r][c + 0] = f2tf32(v.x);
            As[r][c + 1] = f2tf32(v.y);
            As[r][c + 2] = f2tf32(v.z);
            As[r][c + 3] = f2tf32(v.w);
        }
        // B tile: 128 n-rows x 32 k (already tf32-rounded)
        #pragma unroll
        for (int i = 0; i < 4; i++) {
            int idx = tid + 256 * i;
            int r = idx >> 3, c = (idx & 7) * 4;
            float4 v = *(const float4*)(Wt + (size_t)(col0 + r) * K + kk + c);
            Bs[r][c + 0] = __float_as_uint(v.x);
            Bs[r][c + 1] = __float_as_uint(v.y);
            Bs[r][c + 2] = __float_as_uint(v.z);
            Bs[r][c + 3] = __float_as_uint(v.w);
        }
        __syncthreads();
        #pragma unroll
        for (int ks = 0; ks < 4; ks++) {
            int ko = ks * 8;
            uint32_t af[4][4], bfr[4][2];
            #pragma unroll
            for (int mt = 0; mt < 4; mt++) {
                int R = warp_m * 64 + mt * 16 + g;
                af[mt][0] = As[R][ko + qt];
                af[mt][1] = As[R + 8][ko + qt];
                af[mt][2] = As[R][ko + qt + 4];
                af[mt][3] = As[R + 8][ko + qt + 4];
            }
            #pragma unroll
            for (int nt = 0; nt < 4; nt++) {
                int Cc = warp_n * 32 + nt * 8 + g;
                bfr[nt][0] = Bs[Cc][ko + qt];
                bfr[nt][1] = Bs[Cc][ko + qt + 4];
            }
            #pragma unroll
            for (int mt = 0; mt < 4; mt++)
                #pragma unroll
                for (int nt = 0; nt < 4; nt++)
                    mma_tf32(acc[mt][nt], af[mt], bfr[nt]);
        }
        __syncthreads();
    }

    // epilogue
    #pragma unroll
    for (int mt = 0; mt < 4; mt++) {
        int R = row0 + warp_m * 64 + mt * 16 + g;
        #pragma unroll
        for (int nt = 0; nt < 4; nt++) {
            int Cc = col0 + warp_n * 32 + nt * 8 + 2 * qt;
            float c0 = acc[mt][nt][0], c1 = acc[mt][nt][1];
            float c2 = acc[mt][nt][2], c3 = acc[mt][nt][3];
            if (doRelu) {
                c0 = fmaxf(c0, 0.f); c1 = fmaxf(c1, 0.f);
                c2 = fmaxf(c2, 0.f); c3 = fmaxf(c3, 0.f);
            }
            float2 v0 = {c0, c1}, v1 = {c2, c3};
            *(float2*)(C + (size_t)R * N + Cc) = v0;
            *(float2*)(C + (size_t)(R + 8) * N + Cc) = v1;
        }
    }
}

// ---------------- score: AS = adj * sigmoid(relu(ti+tj+e_fc)@w1 + b1) ---------
// one warp per (b,i,j)
__global__ __launch_bounds__(256) void score_kernel(
    const float* __restrict__ P,
    const float* __restrict__ adj1, const float* __restrict__ adj2,
    const float* __restrict__ fc1_w1, const float* __restrict__ fc2_w1,
    const float* __restrict__ fc1_b1, const float* __restrict__ fc2_b1,
    float* __restrict__ AS1, float* __restrict__ AS2) {
    int gw = blockIdx.x * 8 + (threadIdx.x >> 5);   // (b*N + i)*N + j
    int lane = threadIdx.x & 31;
    int j = gw & 127;
    int bi = gw >> 7;            // b*N + i
    int b = gw >> 14;
    const float* Pi = P + (size_t)bi * 1536;
    const float* Pj = P + (size_t)(b * 128 + j) * 1536;
    const float* e1 = g_pre1 + (size_t)gw * 512 + 256;
    const float* e2 = g_pre2 + (size_t)gw * 512 + 256;
    float s1 = 0.f, s2 = 0.f;
    #pragma unroll
    for (int t = 0; t < 4; t++) {
        int p = lane + 32 * t;        // pair index 0..127 -> d = 2p, 2p+1
        float2 f1 = *(const float2*)&e1[2 * p];
        float2 f2 = *(const float2*)&e2[2 * p];
        float2 pi1 = *(const float2*)&Pi[2 * p];
        float2 pj1 = *(const float2*)&Pj[256 + 2 * p];
        float2 pi2 = *(const float2*)&Pi[512 + 2 * p];
        float2 pj2 = *(const float2*)&Pj[768 + 2 * p];
        float2 w1 = *(const float2*)&fc1_w1[2 * p];
        float2 w2 = *(const float2*)&fc2_w1[2 * p];
        s1 = fmaf(fmaxf(pi1.x + pj1.x + f1.x, 0.f), w1.x, s1);
        s1 = fmaf(fmaxf(pi1.y + pj1.y + f1.y, 0.f), w1.y, s1);
        s2 = fmaf(fmaxf(pi2.x + pj2.x + f2.x, 0.f), w2.x, s2);
        s2 = fmaf(fmaxf(pi2.y + pj2.y + f2.y, 0.f), w2.y, s2);
    }
    #pragma unroll
    for (int o = 16; o; o >>= 1) {
        s1 += __shfl_xor_sync(0xffffffffu, s1, o);
        s2 += __shfl_xor_sync(0xffffffffu, s2, o);
    }
    if (lane == 0) {
        float v1 = 1.f / (1.f + __expf(-(s1 + fc1_b1[0])));
        float v2 = 1.f / (1.f + __expf(-(s2 + fc2_b1[0])));
        AS1[gw] = adj1[gw] * v1;
        AS2[gw] = adj2[gw] * v2;
    }
}

// ---------------- aggregate: out1/out2 per (b,i) ------------------------------
__global__ __launch_bounds__(256) void aggregate_kernel(
    const float* __restrict__ P,
    const float* __restrict__ AS1, const float* __restrict__ AS2,
    const float* __restrict__ adj1, const float* __restrict__ adj2,
    float* __restrict__ OC) {
    int bid = blockIdx.x;            // b*N + i
    int tid = threadIdx.x;           // d
    int b = bid >> 7;
    __shared__ float w1s[128], w2s[128], sred[8];
    float d1 = 0.f, d2 = 0.f;
    if (tid < 128) {
        w1s[tid] = AS1[bid * 128 + tid];
        w2s[tid] = AS2[bid * 128 + tid];
        d1 = adj1[bid * 128 + tid];
        d2 = adj2[bid * 128 + tid];
    }
    #pragma unroll
    for (int o = 16; o; o >>= 1) {
        d1 += __shfl_xor_sync(0xffffffffu, d1, o);
        d2 += __shfl_xor_sync(0xffffffffu, d2, o);
    }
    if (tid < 128 && (tid & 31) == 0) {
        sred[tid >> 5] = d1;
        sred[4 + (tid >> 5)] = d2;
    }
    __syncthreads();
    float denom1 = sred[0] + sred[1] + sred[2] + sred[3] + 1.0f;
    float denom2 = sred[4] + sred[5] + sred[6] + sred[7] + 1.0f;

    float acc1 = 0.f, acc2 = 0.f;
    const float* Pb = P + (size_t)(b * 128) * 1536;
    const float* e1 = g_pre1 + (size_t)bid * 128 * 512;
    const float* e2 = g_pre2 + (size_t)bid * 128 * 512;
    for (int j = 0; j < 128; j++) {
        float u1 = Pb[j * 1536 + 1024 + tid];
        float u2 = Pb[j * 1536 + 1280 + tid];
        float f1 = e1[j * 512 + tid];
        float f2 = e2[j * 512 + tid];
        acc1 = fmaf(w1s[j], fmaxf(u1 + f1, 0.f), acc1);
        acc2 = fmaf(w2s[j], fmaxf(u2 + f2, 0.f), acc2);
    }
    OC[(size_t)bid * 512 + tid]       = acc1 / denom1;
    OC[(size_t)bid * 512 + 256 + tid] = acc2 / denom2;
}

// ---------------- relu + residual + bias + layernorm --------------------------
__global__ __launch_bounds__(256) void ln_kernel(
    const float* __restrict__ H, const float* __restrict__ prev,
    const float* __restrict__ bias, const float* __restrict__ gamma,
    const float* __restrict__ beta, float* __restrict__ dst) {
    int row = blockIdx.x, tid = threadIdx.x;
    float v = fmaxf(H[(size_t)row * 256 + tid], 0.f)
              + prev[(size_t)row * 256 + tid] + bias[tid];
    float mean = blockSum256(v) * (1.0f / 256.0f);
    float c = v - mean;
    float var = blockSum256(c * c) * (1.0f / 256.0f);
    dst[(size_t)row * 256 + tid] = c * rsqrtf(var + 1e-5f) * gamma[tid] + beta[tid];
}

// ---------------- self-alignment: outss --------------------------------------
__global__ __launch_bounds__(256) void align_kernel(
    const float* __restrict__ text, const float* __restrict__ textmask,
    const float* __restrict__ AL, const float* __restrict__ abias,
    float* __restrict__ outss) {
    int bid = blockIdx.x;    // b*N + i
    int b = bid >> 7;
    int tid = threadIdx.x;
    __shared__ float xi[256], q[256], lg[128], sred[2];
    xi[tid] = text[(size_t)bid * 256 + tid];
    __syncthreads();
    float acc = 0.f;
    #pragma unroll 4
    for (int k = 0; k < 256; k++) acc = fmaf(xi[k], AL[k * 256 + tid], acc);
    q[tid] = acc;
    __syncthreads();

    int w = tid >> 5, lane = tid & 31;
    for (int j = w * 16; j < w * 16 + 16; j++) {
        const float* tj = text + (size_t)(b * 128 + j) * 256;
        float a = 0.f;
        #pragma unroll
        for (int t = 0; t < 8; t++) {
            int d = lane + 32 * t;
            a = fmaf(q[d], tj[d], a);
        }
        #pragma unroll
        for (int o = 16; o; o >>= 1) a += __shfl_xor_sync(0xffffffffu, a, o);
        if (lane == 0)
            lg[j] = a + (1.0f - textmask[b * 128 + j]) * -1e20f;
    }
    __syncthreads();
    if (tid < 32) {
        float m = -3.4e38f;
        for (int k = tid; k < 128; k += 32) m = fmaxf(m, lg[k]);
        #pragma unroll
        for (int o = 16; o; o >>= 1) m = fmaxf(m, __shfl_xor_sync(0xffffffffu, m, o));
        if (tid == 0) sred[0] = m;
    }
    __syncthreads();
    float mx = sred[0];
    if (tid < 128) lg[tid] = __expf(lg[tid] - mx);
    __syncthreads();
    if (tid < 32) {
        float s = 0.f;
        for (int k = tid; k < 128; k += 32) s += lg[k];
        #pragma unroll
        for (int o = 16; o; o >>= 1) s += __shfl_xor_sync(0xffffffffu, s, o);
        if (tid == 0) sred[1] = s;
    }
    __syncthreads();
    float inv = 1.0f / sred[1];
    float a2 = 0.f;
    for (int j = 0; j < 128; j++)
        a2 = fmaf(lg[j], text[(size_t)(b * 128 + j) * 256 + tid], a2);
    outss[(size_t)bid * 256 + tid] = a2 * inv * textmask[bid] + abias[tid];
}

// ---------------- launch ------------------------------------------------------
extern "C" void kernel_launch(void* const* d_in, const int* in_sizes, int n_in,
                              void* d_out, int out_size) {
    const float* text      = (const float*)d_in[0];
    const float* adj1      = (const float*)d_in[1];
    const float* adj2      = (const float*)d_in[2];
    const float* edge1     = (const float*)d_in[3];
    const float* edge2     = (const float*)d_in[4];
    const float* textmask  = (const float*)d_in[5];
    const float* weight    = (const float*)d_in[6];
    const float* bias      = (const float*)d_in[7];
    const float* gamma     = (const float*)d_in[8];
    const float* beta      = (const float*)d_in[9];
    const float* fuse1_w   = (const float*)d_in[10];
    const float* fuse2_w   = (const float*)d_in[11];
    const float* fc3_w     = (const float*)d_in[12];
    const float* fc1_w0    = (const float*)d_in[13];
    const float* fc1_w1    = (const float*)d_in[14];
    const float* fc1_b1    = (const float*)d_in[15];
    const float* fc2_w0    = (const float*)d_in[16];
    const float* fc2_w1    = (const float*)d_in[17];
    const float* fc2_b1    = (const float*)d_in[18];
    const float* align_lin = (const float*)d_in[19];
    const float* align_bias= (const float*)d_in[20];
    float* out = (float*)d_out;

    float *p_pre1, *p_pre2, *p_Wt1, *p_Wt2, *p_WtP, *p_Wt3, *p_Wtw;
    float *p_P, *p_out, *p_OC, *p_H, *p_AS1, *p_AS2;
    cudaGetSymbolAddress((void**)&p_pre1, g_pre1);
    cudaGetSymbolAddress((void**)&p_pre2, g_pre2);
    cudaGetSymbolAddress((void**)&p_Wt1,  g_Wt1);
    cudaGetSymbolAddress((void**)&p_Wt2,  g_Wt2);
    cudaGetSymbolAddress((void**)&p_WtP,  g_WtP);
    cudaGetSymbolAddress((void**)&p_Wt3,  g_Wt3);
    cudaGetSymbolAddress((void**)&p_Wtw,  g_Wtw);
    cudaGetSymbolAddress((void**)&p_P,    g_P);
    cudaGetSymbolAddress((void**)&p_out,  g_out);
    cudaGetSymbolAddress((void**)&p_OC,   g_OC);
    cudaGetSymbolAddress((void**)&p_H,    g_H);
    cudaGetSymbolAddress((void**)&p_AS1,  g_AS1);
    cudaGetSymbolAddress((void**)&p_AS2,  g_AS2);

    // ---- weight repacks (tf32-rounded fp32, [N][K] layout) ----
    repackT<<<256, 256>>>(fuse1_w + 256 * 256, p_Wt1, 256);              // e1_fuse
    repackT<<<256, 256>>>(fc1_w0 + 512 * 256,  p_Wt1 + 256 * 256, 256);  // e1_fc
    repackT<<<256, 256>>>(fuse2_w + 256 * 256, p_Wt2, 256);
    repackT<<<256, 256>>>(fc2_w0 + 512 * 256,  p_Wt2 + 256 * 256, 256);
    repackT<<<256, 256>>>(fc1_w0,              p_WtP, 256);               // A1
    repackT<<<256, 256>>>(fc1_w0 + 256 * 256,  p_WtP + 256 * 256, 256);   // B1
    repackT<<<256, 256>>>(fc2_w0,              p_WtP + 512 * 256, 256);   // A2
    repackT<<<256, 256>>>(fc2_w0 + 256 * 256,  p_WtP + 768 * 256, 256);   // B2
    repackT<<<256, 256>>>(fuse1_w,             p_WtP + 1024 * 256, 256);  // U1
    repackT<<<256, 256>>>(fuse2_w,             p_WtP + 1280 * 256, 256);  // U2
    repackT<<<256, 512>>>(fc3_w,               p_Wt3, 512);
    repackT<<<256, 256>>>(weight,              p_Wtw, 256);

    // out = relu(text @ weight)
    tgemm<<<dim3(2, 8), 256>>>(text, p_Wtw, p_out, BN2, 256, 256, 1);

    // loop-invariant edge projections (dominant GEMMs) -> fp32 pre
    tgemm<<<dim3(4, 1024), 256>>>(edge1, p_Wt1, p_pre1, ROWS_E, 512, 256, 0);
    tgemm<<<dim3(4, 1024), 256>>>(edge2, p_Wt2, p_pre2, ROWS_E, 512, 256, 0);

    // independent self-alignment output
    align_kernel<<<BN2, 256>>>(text, textmask, align_lin, align_bias,
                               out + BN2 * 256);

    for (int it = 0; it < 3; it++) {
        // 6 fused projections of out: P = out @ Wproj
        tgemm<<<dim3(12, 8), 256>>>(p_out, p_WtP, p_P, BN2, 1536, 256, 0);
        score_kernel<<<ROWS_E / 8, 256>>>(p_P, adj1, adj2, fc1_w1, fc2_w1,
                                          fc1_b1, fc2_b1, p_AS1, p_AS2);
        aggregate_kernel<<<BN2, 256>>>(p_P, p_AS1, p_AS2, adj1, adj2, p_OC);
        // H = [out1|out2] @ fc3_w
        tgemm<<<dim3(2, 8), 256>>>(p_OC, p_Wt3, p_H, BN2, 256, 512, 0);
        float* dst = (it == 2) ? out : p_out;
        ln_kernel<<<BN2, 256>>>(p_H, p_out, bias, gamma, beta, dst);
    }
}

// round 5
// speedup vs baseline: 2.5331x; 1.1249x over previous
#include <cuda_runtime.h>
#include <cuda_fp16.h>
#include <math.h>
#include <stdint.h>

// B=8, N=128, D=256
#define BN2 1024           // B*N
#define ROWS_E 131072      // B*N*N

// ---------------- scratch (device globals; no allocation allowed) -------------
__device__ __half g_pre1h[67108864]; // [B*N*N, 512] fp16: 0..255 fuse, 256..511 fc
__device__ __half g_pre2h[67108864];
__device__ float g_Wt1[512 * 256];   // [N][K], tf32-rounded fp32
__device__ float g_Wt2[512 * 256];
__device__ float g_WtP[1536 * 256];
__device__ float g_Wt3[256 * 512];
__device__ float g_Wtw[256 * 256];
__device__ float g_P[1024 * 1536];   // projections of `out`: [A1|B1|A2|B2|U1|U2]
__device__ float g_out[1024 * 256];
__device__ float g_OC[1024 * 512];   // [out1 | out2]
__device__ float g_H[1024 * 256];
__device__ float g_AS1[131072];      // adj1 * sigmoid(s1)
__device__ float g_AS2[131072];

// ---------------- helpers ----------------------------------------------------
__device__ __forceinline__ float blockSum256(float v) {
    __shared__ float red[8];
    #pragma unroll
    for (int o = 16; o; o >>= 1) v += __shfl_xor_sync(0xffffffffu, v, o);
    if ((threadIdx.x & 31) == 0) red[threadIdx.x >> 5] = v;
    __syncthreads();
    float s = red[0];
    #pragma unroll
    for (int k = 1; k < 8; k++) s += red[k];
    __syncthreads();
    return s;
}

__device__ __forceinline__ uint32_t f2tf32(float x) {
    uint32_t r;
    asm("cvt.rna.tf32.f32 %0, %1;" : "=r"(r) : "f"(x));
    return r;
}

__device__ __forceinline__ void mma_tf32(float* d, const uint32_t* a, const uint32_t* b) {
    asm volatile(
        "mma.sync.aligned.m16n8k8.row.col.f32.tf32.tf32.f32 "
        "{%0,%1,%2,%3}, {%4,%5,%6,%7}, {%8,%9}, {%0,%1,%2,%3};\n"
        : "+f"(d[0]), "+f"(d[1]), "+f"(d[2]), "+f"(d[3])
        : "r"(a[0]), "r"(a[1]), "r"(a[2]), "r"(a[3]), "r"(b[0]), "r"(b[1]));
}

__device__ __forceinline__ void cp16(uint32_t dst, const void* src) {
    asm volatile("cp.async.cg.shared.global [%0], [%1], 16;\n" :: "r"(dst), "l"(src));
}

// ---------------- weight repack: dst[n][k] = tf32(src[k*256 + n]) -------------
__global__ void repackT(const float* __restrict__ src, float* __restrict__ dst,
                        int K) {
    int n = blockIdx.x;     // 0..255 (segment-local column)
    int k = threadIdx.x;    // 0..K-1
    uint32_t v = f2tf32(src[k * 256 + n]);
    dst[n * K + k] = __uint_as_float(v);
}

// ---------------- tf32 tensor GEMM: C[M,N] = A_f32[M,K] @ Wt[N,K]^T -----------
// 128x128 tile, BK=32, 256 threads (8 warps, 2x4), each warp 64x32 via
// m16n8k8 tf32 mma. 2-stage cp.async pipeline; A raw fp32 in smem, rounded
// to tf32 (rna) at fragment-load time; Wt pre-rounded.
// Output: fp32 C and/or fp16 Ch.
#define STAGE_U32 4608          // 128 * 36 floats per stage
__global__ __launch_bounds__(256, 2) void tgemm(
    const float* __restrict__ A, const float* __restrict__ Wt,
    float* __restrict__ C, __half* __restrict__ Ch,
    int M, int N, int K, int doRelu) {
    extern __shared__ uint32_t sh[];
    uint32_t* As = sh;                     // [2][128][36]
    uint32_t* Bs = sh + 2 * STAGE_U32;     // [2][128][36]
    const int tid = threadIdx.x;
    const int wid = tid >> 5, lane = tid & 31;
    const int g = lane >> 2, qt = lane & 3;
    const int warp_m = wid & 1, warp_n = wid >> 1;
    const int row0 = blockIdx.y * 128;
    const int col0 = blockIdx.x * 128;

    const uint32_t aAddr = (uint32_t)__cvta_generic_to_shared(As);
    const uint32_t bAddr = (uint32_t)__cvta_generic_to_shared(Bs);
    const int ldr = tid >> 3;              // 0..31 rows per 256-chunk group
    const int ldc = (tid & 7) * 4;

    float acc[4][4][4];
    #pragma unroll
    for (int i = 0; i < 4; i++)
        #pragma unroll
        for (int j = 0; j < 4; j++)
            #pragma unroll
            for (int r = 0; r < 4; r++) acc[i][j][r] = 0.f;

    const int KT = K >> 5;

    // prologue: stage 0
    {
        #pragma unroll
        for (int i = 0; i < 4; i++) {
            int r = ldr + 32 * i;
            cp16(aAddr + (uint32_t)(r * 36 + ldc) * 4,
                 A + (size_t)(row0 + r) * K + ldc);
            cp16(bAddr + (uint32_t)(r * 36 + ldc) * 4,
                 Wt + (size_t)(col0 + r) * K + ldc);
        }
        asm volatile("cp.async.commit_group;\n");
    }

    for (int kt = 0; kt < KT; kt++) {
        if (kt + 1 < KT) {
            int kk = (kt + 1) << 5;
            uint32_t so = (uint32_t)(((kt + 1) & 1) * STAGE_U32 * 4);
            #pragma unroll
            for (int i = 0; i < 4; i++) {
                int r = ldr + 32 * i;
                cp16(aAddr + so + (uint32_t)(r * 36 + ldc) * 4,
                     A + (size_t)(row0 + r) * K + kk + ldc);
                cp16(bAddr + so + (uint32_t)(r * 36 + ldc) * 4,
                     Wt + (size_t)(col0 + r) * K + kk + ldc);
            }
            asm volatile("cp.async.commit_group;\n");
            asm volatile("cp.async.wait_group 1;\n");
        } else {
            asm volatile("cp.async.wait_group 0;\n");
        }
        __syncthreads();

        const uint32_t* Ac = As + (kt & 1) * STAGE_U32;
        const uint32_t* Bc = Bs + (kt & 1) * STAGE_U32;
        #pragma unroll
        for (int ks = 0; ks < 4; ks++) {
            int ko = ks * 8;
            uint32_t af[4][4], bfr[4][2];
            #pragma unroll
            for (int mt = 0; mt < 4; mt++) {
                int R = warp_m * 64 + mt * 16 + g;
                af[mt][0] = f2tf32(__uint_as_float(Ac[R * 36 + ko + qt]));
                af[mt][1] = f2tf32(__uint_as_float(Ac[(R + 8) * 36 + ko + qt]));
                af[mt][2] = f2tf32(__uint_as_float(Ac[R * 36 + ko + qt + 4]));
                af[mt][3] = f2tf32(__uint_as_float(Ac[(R + 8) * 36 + ko + qt + 4]));
            }
            #pragma unroll
            for (int nt = 0; nt < 4; nt++) {
                int Cc = warp_n * 32 + nt * 8 + g;
                bfr[nt][0] = Bc[Cc * 36 + ko + qt];
                bfr[nt][1] = Bc[Cc * 36 + ko + qt + 4];
            }
            #pragma unroll
            for (int mt = 0; mt < 4; mt++)
                #pragma unroll
                for (int nt = 0; nt < 4; nt++)
                    mma_tf32(acc[mt][nt], af[mt], bfr[nt]);
        }
        __syncthreads();
    }

    // epilogue
    #pragma unroll
    for (int mt = 0; mt < 4; mt++) {
        int R = row0 + warp_m * 64 + mt * 16 + g;
        #pragma unroll
        for (int nt = 0; nt < 4; nt++) {
            int Cc = col0 + warp_n * 32 + nt * 8 + 2 * qt;
            float c0 = acc[mt][nt][0], c1 = acc[mt][nt][1];
            float c2 = acc[mt][nt][2], c3 = acc[mt][nt][3];
            if (doRelu) {
                c0 = fmaxf(c0, 0.f); c1 = fmaxf(c1, 0.f);
                c2 = fmaxf(c2, 0.f); c3 = fmaxf(c3, 0.f);
            }
            if (C) {
                float2 v0 = {c0, c1}, v1 = {c2, c3};
                *(float2*)(C + (size_t)R * N + Cc) = v0;
                *(float2*)(C + (size_t)(R + 8) * N + Cc) = v1;
            }
            if (Ch) {
                *(__half2*)(Ch + (size_t)R * N + Cc) = __floats2half2_rn(c0, c1);
                *(__half2*)(Ch + (size_t)(R + 8) * N + Cc) = __floats2half2_rn(c2, c3);
            }
        }
    }
}

// ---------------- score: AS = adj * sigmoid(relu(ti+tj+e_fc)@w1 + b1) ---------
// one warp per (b,i,j); e_fc read as fp16
__global__ __launch_bounds__(256) void score_kernel(
    const float* __restrict__ P,
    const float* __restrict__ adj1, const float* __restrict__ adj2,
    const float* __restrict__ fc1_w1, const float* __restrict__ fc2_w1,
    const float* __restrict__ fc1_b1, const float* __restrict__ fc2_b1,
    float* __restrict__ AS1, float* __restrict__ AS2) {
    int gw = blockIdx.x * 8 + (threadIdx.x >> 5);   // (b*N + i)*N + j
    int lane = threadIdx.x & 31;
    int j = gw & 127;
    int bi = gw >> 7;            // b*N + i
    int b = gw >> 14;
    const float* Pi = P + (size_t)bi * 1536;
    const float* Pj = P + (size_t)(b * 128 + j) * 1536;
    const __half2* e1 = (const __half2*)(g_pre1h + (size_t)gw * 512 + 256);
    const __half2* e2 = (const __half2*)(g_pre2h + (size_t)gw * 512 + 256);
    float s1 = 0.f, s2 = 0.f;
    #pragma unroll
    for (int t = 0; t < 4; t++) {
        int p = lane + 32 * t;        // pair index 0..127 -> d = 2p, 2p+1
        float2 f1 = __half22float2(e1[p]);
        float2 f2 = __half22float2(e2[p]);
        float2 pi1 = *(const float2*)&Pi[2 * p];
        float2 pj1 = *(const float2*)&Pj[256 + 2 * p];
        float2 pi2 = *(const float2*)&Pi[512 + 2 * p];
        float2 pj2 = *(const float2*)&Pj[768 + 2 * p];
        float2 w1 = *(const float2*)&fc1_w1[2 * p];
        float2 w2 = *(const float2*)&fc2_w1[2 * p];
        s1 = fmaf(fmaxf(pi1.x + pj1.x + f1.x, 0.f), w1.x, s1);
        s1 = fmaf(fmaxf(pi1.y + pj1.y + f1.y, 0.f), w1.y, s1);
        s2 = fmaf(fmaxf(pi2.x + pj2.x + f2.x, 0.f), w2.x, s2);
        s2 = fmaf(fmaxf(pi2.y + pj2.y + f2.y, 0.f), w2.y, s2);
    }
    #pragma unroll
    for (int o = 16; o; o >>= 1) {
        s1 += __shfl_xor_sync(0xffffffffu, s1, o);
        s2 += __shfl_xor_sync(0xffffffffu, s2, o);
    }
    if (lane == 0) {
        float v1 = 1.f / (1.f + __expf(-(s1 + fc1_b1[0])));
        float v2 = 1.f / (1.f + __expf(-(s2 + fc2_b1[0])));
        AS1[gw] = adj1[gw] * v1;
        AS2[gw] = adj2[gw] * v2;
    }
}

// ---------------- aggregate: out1/out2 per (b,i) ------------------------------
__global__ __launch_bounds__(256) void aggregate_kernel(
    const float* __restrict__ P,
    const float* __restrict__ AS1, const float* __restrict__ AS2,
    const float* __restrict__ adj1, const float* __restrict__ adj2,
    float* __restrict__ OC) {
    int bid = blockIdx.x;            // b*N + i
    int tid = threadIdx.x;           // d
    int b = bid >> 7;
    __shared__ float w1s[128], w2s[128], sred[8];
    float d1 = 0.f, d2 = 0.f;
    if (tid < 128) {
        w1s[tid] = AS1[bid * 128 + tid];
        w2s[tid] = AS2[bid * 128 + tid];
        d1 = adj1[bid * 128 + tid];
        d2 = adj2[bid * 128 + tid];
    }
    #pragma unroll
    for (int o = 16; o; o >>= 1) {
        d1 += __shfl_xor_sync(0xffffffffu, d1, o);
        d2 += __shfl_xor_sync(0xffffffffu, d2, o);
    }
    if (tid < 128 && (tid & 31) == 0) {
        sred[tid >> 5] = d1;
        sred[4 + (tid >> 5)] = d2;
    }
    __syncthreads();
    float denom1 = sred[0] + sred[1] + sred[2] + sred[3] + 1.0f;
    float denom2 = sred[4] + sred[5] + sred[6] + sred[7] + 1.0f;

    float acc1 = 0.f, acc2 = 0.f;
    const float* Pb = P + (size_t)(b * 128) * 1536;
    const __half* e1 = g_pre1h + (size_t)bid * 128 * 512;
    const __half* e2 = g_pre2h + (size_t)bid * 128 * 512;
    #pragma unroll 4
    for (int j = 0; j < 128; j++) {
        float u1 = Pb[j * 1536 + 1024 + tid];
        float u2 = Pb[j * 1536 + 1280 + tid];
        float f1 = __half2float(e1[j * 512 + tid]);
        float f2 = __half2float(e2[j * 512 + tid]);
        acc1 = fmaf(w1s[j], fmaxf(u1 + f1, 0.f), acc1);
        acc2 = fmaf(w2s[j], fmaxf(u2 + f2, 0.f), acc2);
    }
    OC[(size_t)bid * 512 + tid]       = acc1 / denom1;
    OC[(size_t)bid * 512 + 256 + tid] = acc2 / denom2;
}

// ---------------- relu + residual + bias + layernorm --------------------------
__global__ __launch_bounds__(256) void ln_kernel(
    const float* __restrict__ H, const float* __restrict__ prev,
    const float* __restrict__ bias, const float* __restrict__ gamma,
    const float* __restrict__ beta, float* __restrict__ dst) {
    int row = blockIdx.x, tid = threadIdx.x;
    float v = fmaxf(H[(size_t)row * 256 + tid], 0.f)
              + prev[(size_t)row * 256 + tid] + bias[tid];
    float mean = blockSum256(v) * (1.0f / 256.0f);
    float c = v - mean;
    float var = blockSum256(c * c) * (1.0f / 256.0f);
    dst[(size_t)row * 256 + tid] = c * rsqrtf(var + 1e-5f) * gamma[tid] + beta[tid];
}

// ---------------- self-alignment: outss --------------------------------------
__global__ __launch_bounds__(256) void align_kernel(
    const float* __restrict__ text, const float* __restrict__ textmask,
    const float* __restrict__ AL, const float* __restrict__ abias,
    float* __restrict__ outss) {
    int bid = blockIdx.x;    // b*N + i
    int b = bid >> 7;
    int tid = threadIdx.x;
    __shared__ float xi[256], q[256], lg[128], sred[2];
    xi[tid] = text[(size_t)bid * 256 + tid];
    __syncthreads();
    float acc = 0.f;
    #pragma unroll 4
    for (int k = 0; k < 256; k++) acc = fmaf(xi[k], AL[k * 256 + tid], acc);
    q[tid] = acc;
    __syncthreads();

    int w = tid >> 5, lane = tid & 31;
    for (int j = w * 16; j < w * 16 + 16; j++) {
        const float* tj = text + (size_t)(b * 128 + j) * 256;
        float a = 0.f;
        #pragma unroll
        for (int t = 0; t < 8; t++) {
            int d = lane + 32 * t;
            a = fmaf(q[d], tj[d], a);
        }
        #pragma unroll
        for (int o = 16; o; o >>= 1) a += __shfl_xor_sync(0xffffffffu, a, o);
        if (lane == 0)
            lg[j] = a + (1.0f - textmask[b * 128 + j]) * -1e20f;
    }
    __syncthreads();
    if (tid < 32) {
        float m = -3.4e38f;
        for (int k = tid; k < 128; k += 32) m = fmaxf(m, lg[k]);
        #pragma unroll
        for (int o = 16; o; o >>= 1) m = fmaxf(m, __shfl_xor_sync(0xffffffffu, m, o));
        if (tid == 0) sred[0] = m;
    }
    __syncthreads();
    float mx = sred[0];
    if (tid < 128) lg[tid] = __expf(lg[tid] - mx);
    __syncthreads();
    if (tid < 32) {
        float s = 0.f;
        for (int k = tid; k < 128; k += 32) s += lg[k];
        #pragma unroll
        for (int o = 16; o; o >>= 1) s += __shfl_xor_sync(0xffffffffu, s, o);
        if (tid == 0) sred[1] = s;
    }
    __syncthreads();
    float inv = 1.0f / sred[1];
    float a2 = 0.f;
    for (int j = 0; j < 128; j++)
        a2 = fmaf(lg[j], text[(size_t)(b * 128 + j) * 256 + tid], a2);
    outss[(size_t)bid * 256 + tid] = a2 * inv * textmask[bid] + abias[tid];
}

// ---------------- launch ------------------------------------------------------
#define TGEMM_SMEM 73728

extern "C" void kernel_launch(void* const* d_in, const int* in_sizes, int n_in,
                              void* d_out, int out_size) {
    const float* text      = (const float*)d_in[0];
    const float* adj1      = (const float*)d_in[1];
    const float* adj2      = (const float*)d_in[2];
    const float* edge1     = (const float*)d_in[3];
    const float* edge2     = (const float*)d_in[4];
    const float* textmask  = (const float*)d_in[5];
    const float* weight    = (const float*)d_in[6];
    const float* bias      = (const float*)d_in[7];
    const float* gamma     = (const float*)d_in[8];
    const float* beta      = (const float*)d_in[9];
    const float* fuse1_w   = (const float*)d_in[10];
    const float* fuse2_w   = (const float*)d_in[11];
    const float* fc3_w     = (const float*)d_in[12];
    const float* fc1_w0    = (const float*)d_in[13];
    const float* fc1_w1    = (const float*)d_in[14];
    const float* fc1_b1    = (const float*)d_in[15];
    const float* fc2_w0    = (const float*)d_in[16];
    const float* fc2_w1    = (const float*)d_in[17];
    const float* fc2_b1    = (const float*)d_in[18];
    const float* align_lin = (const float*)d_in[19];
    const float* align_bias= (const float*)d_in[20];
    float* out = (float*)d_out;

    static int attr_done = 0;
    if (!attr_done) {
        cudaFuncSetAttribute(tgemm, cudaFuncAttributeMaxDynamicSharedMemorySize,
                             TGEMM_SMEM);
        attr_done = 1;
    }

    __half *p_pre1, *p_pre2;
    float *p_Wt1, *p_Wt2, *p_WtP, *p_Wt3, *p_Wtw;
    float *p_P, *p_out, *p_OC, *p_H, *p_AS1, *p_AS2;
    cudaGetSymbolAddress((void**)&p_pre1, g_pre1h);
    cudaGetSymbolAddress((void**)&p_pre2, g_pre2h);
    cudaGetSymbolAddress((void**)&p_Wt1,  g_Wt1);
    cudaGetSymbolAddress((void**)&p_Wt2,  g_Wt2);
    cudaGetSymbolAddress((void**)&p_WtP,  g_WtP);
    cudaGetSymbolAddress((void**)&p_Wt3,  g_Wt3);
    cudaGetSymbolAddress((void**)&p_Wtw,  g_Wtw);
    cudaGetSymbolAddress((void**)&p_P,    g_P);
    cudaGetSymbolAddress((void**)&p_out,  g_out);
    cudaGetSymbolAddress((void**)&p_OC,   g_OC);
    cudaGetSymbolAddress((void**)&p_H,    g_H);
    cudaGetSymbolAddress((void**)&p_AS1,  g_AS1);
    cudaGetSymbolAddress((void**)&p_AS2,  g_AS2);

    // ---- weight repacks (tf32-rounded fp32, [N][K] layout) ----
    repackT<<<256, 256>>>(fuse1_w + 256 * 256, p_Wt1, 256);              // e1_fuse
    repackT<<<256, 256>>>(fc1_w0 + 512 * 256,  p_Wt1 + 256 * 256, 256);  // e1_fc
    repackT<<<256, 256>>>(fuse2_w + 256 * 256, p_Wt2, 256);
    repackT<<<256, 256>>>(fc2_w0 + 512 * 256,  p_Wt2 + 256 * 256, 256);
    repackT<<<256, 256>>>(fc1_w0,              p_WtP, 256);               // A1
    repackT<<<256, 256>>>(fc1_w0 + 256 * 256,  p_WtP + 256 * 256, 256);   // B1
    repackT<<<256, 256>>>(fc2_w0,              p_WtP + 512 * 256, 256);   // A2
    repackT<<<256, 256>>>(fc2_w0 + 256 * 256,  p_WtP + 768 * 256, 256);   // B2
    repackT<<<256, 256>>>(fuse1_w,             p_WtP + 1024 * 256, 256);  // U1
    repackT<<<256, 256>>>(fuse2_w,             p_WtP + 1280 * 256, 256);  // U2
    repackT<<<256, 512>>>(fc3_w,               p_Wt3, 512);
    repackT<<<256, 256>>>(weight,              p_Wtw, 256);

    // out = relu(text @ weight)
    tgemm<<<dim3(2, 8), 256, TGEMM_SMEM>>>(text, p_Wtw, p_out, (__half*)0,
                                           BN2, 256, 256, 1);

    // loop-invariant edge projections (dominant GEMMs) -> fp16 pre
    tgemm<<<dim3(4, 1024), 256, TGEMM_SMEM>>>(edge1, p_Wt1, (float*)0, p_pre1,
                                              ROWS_E, 512, 256, 0);
    tgemm<<<dim3(4, 1024), 256, TGEMM_SMEM>>>(edge2, p_Wt2, (float*)0, p_pre2,
                                              ROWS_E, 512, 256, 0);

    // independent self-alignment output
    align_kernel<<<BN2, 256>>>(text, textmask, align_lin, align_bias,
                               out + BN2 * 256);

    for (int it = 0; it < 3; it++) {
        // 6 fused projections of out: P = out @ Wproj
        tgemm<<<dim3(12, 8), 256, TGEMM_SMEM>>>(p_out, p_WtP, p_P, (__half*)0,
                                                BN2, 1536, 256, 0);
        score_kernel<<<ROWS_E / 8, 256>>>(p_P, adj1, adj2, fc1_w1, fc2_w1,
                                          fc1_b1, fc2_b1, p_AS1, p_AS2);
        aggregate_kernel<<<BN2, 256>>>(p_P, p_AS1, p_AS2, adj1, adj2, p_OC);
        // H = [out1|out2] @ fc3_w
        tgemm<<<dim3(2, 8), 256, TGEMM_SMEM>>>(p_OC, p_Wt3, p_H, (__half*)0,
                                               BN2, 256, 512, 0);
        float* dst = (it == 2) ? out : p_out;
        ln_kernel<<<BN2, 256>>>(p_H, p_out, bias, gamma, beta, dst);
    }
}